// round 2
// baseline (speedup 1.0000x reference)
#include <cuda_runtime.h>
#include <math.h>

#define Bsz 4096
#define Dd  66
#define Hh  512

// Scratch (allocation-free rule: __device__ globals)
__device__ float g_h1[Bsz * Hh];
__device__ float g_s1[Bsz * Hh];
__device__ float g_h2[Bsz * Hh];
__device__ float g_s2[Bsz * Hh];
__device__ float g_u [Bsz * Hh];
__device__ float g_C [Hh * Hh];

// C[i,j] = W2[i,j] * sum_{d<66} W3[j,d] * W1[d,i]
// thread.x -> j (coalesced store), thread.y -> i (W1 broadcast within warp)
__global__ void precompute_C(const float* __restrict__ W1,
                             const float* __restrict__ W2,
                             const float* __restrict__ W3) {
    int j = blockIdx.x * 32 + threadIdx.x;
    int i = blockIdx.y * 8  + threadIdx.y;
    float acc = 0.f;
#pragma unroll
    for (int d = 0; d < Dd; d++)
        acc = fmaf(W3[j * Dd + d], W1[d * Hh + i], acc);
    g_C[i * Hh + j] = W2[i * Hh + j] * acc;
}

// Fused tiled SGEMM: out = act(A @ Bm + bias)
// MODE 0: plain (no bias)          -> out0
// MODE 1: silu                     -> out0 = silu(x), out1 = silu'(x)
// MODE 2: bias only                -> out0 = x + bias
// MODE 3: concat([A, tcol]) + silu -> like MODE 1, A is [M x Dd], col Dd is tcol
template<int MODE>
__global__ void __launch_bounds__(256, 2)
gemm_fused(const float* __restrict__ A, const float* __restrict__ tcol,
           const float* __restrict__ Bm, const float* __restrict__ bias,
           float* __restrict__ out0, float* __restrict__ out1,
           int M, int N, int K)
{
    __shared__ float As[8][132];   // transposed, padded to kill STS conflicts
    __shared__ float Bs[8][128];

    const int tid = threadIdx.x;
    const int ty = tid >> 4;       // 0..15
    const int tx = tid & 15;       // 0..15
    const int rowBase = blockIdx.y * 128;
    const int colBase = blockIdx.x * 128;

    float acc[8][8];
#pragma unroll
    for (int m = 0; m < 8; m++)
#pragma unroll
        for (int n = 0; n < 8; n++) acc[m][n] = 0.f;

    for (int k0 = 0; k0 < K; k0 += 8) {
        // A tile: 128 rows x 8 cols -> As[c][r]
#pragma unroll
        for (int i = 0; i < 4; i++) {
            int e = tid + i * 256;
            int r = e >> 3, c = e & 7;
            int gk = k0 + c;
            int gr = rowBase + r;
            float v = 0.f;
            if (MODE == 3) {
                if (gk < Dd)       v = A[gr * Dd + gk];
                else if (gk == Dd) v = tcol[gr];
            } else {
                if (gk < K)        v = A[gr * K + gk];
            }
            As[c][r] = v;
        }
        // B tile: 8 rows x 128 cols
#pragma unroll
        for (int i = 0; i < 4; i++) {
            int e = tid + i * 256;
            int r = e >> 7, c = e & 127;
            int gk = k0 + r;
            int gc = colBase + c;
            float v = 0.f;
            if (gk < K && gc < N) v = Bm[gk * N + gc];
            Bs[r][c] = v;
        }
        __syncthreads();

#pragma unroll
        for (int k = 0; k < 8; k++) {
            float4 a0 = *(const float4*)&As[k][ty * 8];
            float4 a1 = *(const float4*)&As[k][ty * 8 + 4];
            float4 b0 = *(const float4*)&Bs[k][tx * 8];
            float4 b1 = *(const float4*)&Bs[k][tx * 8 + 4];
            float ra[8] = {a0.x, a0.y, a0.z, a0.w, a1.x, a1.y, a1.z, a1.w};
            float rb[8] = {b0.x, b0.y, b0.z, b0.w, b1.x, b1.y, b1.z, b1.w};
#pragma unroll
            for (int m = 0; m < 8; m++)
#pragma unroll
                for (int n = 0; n < 8; n++)
                    acc[m][n] = fmaf(ra[m], rb[n], acc[m][n]);
        }
        __syncthreads();
    }

#pragma unroll
    for (int m = 0; m < 8; m++) {
        int gr = rowBase + ty * 8 + m;
#pragma unroll
        for (int n = 0; n < 8; n++) {
            int gc = colBase + tx * 8 + n;
            if (gc >= N) continue;
            float x = acc[m][n];
            if (MODE == 1 || MODE == 3) {
                x += bias[gc];
                float s = 1.f / (1.f + __expf(-x));
                out0[gr * N + gc] = x * s;                       // silu
                out1[gr * N + gc] = s * (1.f + x * (1.f - s));   // silu'
            } else if (MODE == 2) {
                out0[gr * N + gc] = x + bias[gc];
            } else {
                out0[gr * N + gc] = x;
            }
        }
    }
}

// div[b] = sum_j u[b,j] * s2[b,j];  out[b] = -div[b]
__global__ void div_reduce(const float* __restrict__ u,
                           const float* __restrict__ s2,
                           float* __restrict__ out) {
    int b    = blockIdx.x * 8 + (threadIdx.x >> 5);
    int lane = threadIdx.x & 31;
    const float* up = u  + b * Hh;
    const float* sp = s2 + b * Hh;
    float acc = 0.f;
#pragma unroll
    for (int i = 0; i < Hh / 32; i++)
        acc = fmaf(up[lane + 32 * i], sp[lane + 32 * i], acc);
#pragma unroll
    for (int o = 16; o; o >>= 1)
        acc += __shfl_xor_sync(0xffffffffu, acc, o);
    if (lane == 0) out[b] = -acc;
}

extern "C" void kernel_launch(void* const* d_in, const int* in_sizes, int n_in,
                              void* d_out, int out_size) {
    const float* xs = (const float*)d_in[0];
    const float* t  = (const float*)d_in[1];
    const float* W1 = (const float*)d_in[2];
    const float* b1 = (const float*)d_in[3];
    const float* W2 = (const float*)d_in[4];
    const float* b2 = (const float*)d_in[5];
    const float* W3 = (const float*)d_in[6];
    const float* b3 = (const float*)d_in[7];
    float* out = (float*)d_out;

    float *h1, *s1, *h2, *s2, *u, *C;
    cudaGetSymbolAddress((void**)&h1, g_h1);
    cudaGetSymbolAddress((void**)&s1, g_s1);
    cudaGetSymbolAddress((void**)&h2, g_h2);
    cudaGetSymbolAddress((void**)&s2, g_s2);
    cudaGetSymbolAddress((void**)&u,  g_u);
    cudaGetSymbolAddress((void**)&C,  g_C);

    // C = W2 .* (W3 @ W1[:D])^T   (batch-independent)
    precompute_C<<<dim3(16, 64), dim3(32, 8)>>>(W1, W2, W3);

    // layer 1: a1 = [xs|t] @ W1 + b1 ; h1 = silu(a1), s1 = silu'(a1)
    gemm_fused<3><<<dim3(4, 32), 256>>>(xs, t, W1, b1, h1, s1, Bsz, Hh, Dd + 1);
    // layer 2: a2 = h1 @ W2 + b2 ; h2, s2
    gemm_fused<1><<<dim3(4, 32), 256>>>(h1, nullptr, W2, b2, h2, s2, Bsz, Hh, Hh);
    // layer 3: dxs = h2 @ W3 + b3  -> directly into d_out[0 : B*D]
    gemm_fused<2><<<dim3(1, 32), 256>>>(h2, nullptr, W3, b3, out, nullptr, Bsz, Dd, Hh);
    // u = s1 @ C
    gemm_fused<0><<<dim3(4, 32), 256>>>(s1, nullptr, C, nullptr, u, nullptr, Bsz, Hh, Hh);
    // -div -> d_out[B*D : B*D + B]
    div_reduce<<<512, 256>>>(u, s2, out + Bsz * Dd);
}

// round 3
// speedup vs baseline: 1.1480x; 1.1480x over previous
#include <cuda_runtime.h>
#include <math.h>

#define Bsz 4096
#define Dd  66
#define Hh  512

// Scratch (allocation-free rule: __device__ globals)
__device__ float g_h1[Bsz * Hh];
__device__ float g_s1[Bsz * Hh];
__device__ float g_h2[Bsz * Hh];
__device__ float g_s2[Bsz * Hh];
__device__ float g_C [Hh * Hh];
__device__ float g_dp[4 * Bsz];

// packed fp32x2 FMA (Blackwell sm_103a): d = a*b + d elementwise on {lo,hi}
#define FMA2(d, a, b) \
    asm("fma.rn.f32x2 %0, %1, %2, %0;" : "+l"(d) : "l"(a), "l"(b))

// C[i,j] = W2[i,j] * sum_{d<66} W3[j,d] * W1[d,i]
__global__ void precompute_C(const float* __restrict__ W1,
                             const float* __restrict__ W2,
                             const float* __restrict__ W3) {
    int j = blockIdx.x * 32 + threadIdx.x;
    int i = blockIdx.y * 8  + threadIdx.y;
    float acc = 0.f;
#pragma unroll
    for (int d = 0; d < Dd; d++)
        acc = fmaf(W3[j * Dd + d], W1[d * Hh + i], acc);
    g_C[i * Hh + j] = W2[i * Hh + j] * acc;
}

__device__ __forceinline__ float4 loadA_concat(const float* __restrict__ A,
                                               const float* __restrict__ tcol,
                                               int gr, int gk0) {
    float v[4];
#pragma unroll
    for (int j = 0; j < 4; j++) {
        int gk = gk0 + j;
        v[j] = (gk < Dd) ? A[gr * Dd + gk] : (gk == Dd ? tcol[gr] : 0.f);
    }
    return make_float4(v[0], v[1], v[2], v[3]);
}

// Tiled SGEMM with FFMA2 inner loop, 128x128 tile, BK=8, double-buffered.
// MODE 3: A = concat([xs, t]) (K=67), epilogue silu + silu' -> out0, out1
// MODE 1: epilogue silu + silu' -> out0, out1
// MODE 0: no bias/act; epilogue: dot row-tile with s2d, write partial div -> dpart
template<int MODE>
__global__ void __launch_bounds__(256)
gemm2(const float* __restrict__ A, const float* __restrict__ tcol,
      const float* __restrict__ Bm, const float* __restrict__ bias,
      float* __restrict__ out0, float* __restrict__ out1,
      const float* __restrict__ s2d, float* __restrict__ dpart,
      int K)
{
    // As holds the A tile transposed AND duplicated: As[k][2r]=As[k][2r+1]=a(r,k)
    __shared__ __align__(16) float As[2][8][258];
    __shared__ __align__(16) float Bs[2][8][128];

    const int tid = threadIdx.x;
    const int tx = tid & 15;       // col group (8 cols each)
    const int ty = tid >> 4;       // row group (8 rows each)
    const int rowBase = blockIdx.y * 128;
    const int colBase = blockIdx.x * 128;
    const int N = Hh;

    // loader mapping
    const int ar = tid >> 1;          // A row within tile (0..127)
    const int ac = (tid & 1) * 4;     // A k-col start {0,4}
    const int br = tid >> 5;          // B k-row (0..7)
    const int bc = (tid & 31) * 4;    // B col start

    unsigned long long acc[8][4];
#pragma unroll
    for (int m = 0; m < 8; m++)
#pragma unroll
        for (int p = 0; p < 4; p++) acc[m][p] = 0ull;

    const int KT = (K + 7) >> 3;
    float4 aF, bF;

    // prefetch + store tile 0
    {
        if (MODE == 3) aF = loadA_concat(A, tcol, rowBase + ar, ac);
        else           aF = *(const float4*)&A[(rowBase + ar) * K + ac];
        int gk = br;
        bF = (gk < K) ? *(const float4*)&Bm[gk * N + colBase + bc]
                      : make_float4(0.f, 0.f, 0.f, 0.f);
        *(float2*)&As[0][ac + 0][2 * ar] = make_float2(aF.x, aF.x);
        *(float2*)&As[0][ac + 1][2 * ar] = make_float2(aF.y, aF.y);
        *(float2*)&As[0][ac + 2][2 * ar] = make_float2(aF.z, aF.z);
        *(float2*)&As[0][ac + 3][2 * ar] = make_float2(aF.w, aF.w);
        *(float4*)&Bs[0][br][bc] = bF;
    }
    __syncthreads();

    for (int kt = 0; kt < KT; kt++) {
        const int cur = kt & 1;
        if (kt + 1 < KT) {
            const int k0 = (kt + 1) * 8;
            if (MODE == 3) aF = loadA_concat(A, tcol, rowBase + ar, k0 + ac);
            else           aF = *(const float4*)&A[(rowBase + ar) * K + k0 + ac];
            int gk = k0 + br;
            bF = (gk < K) ? *(const float4*)&Bm[gk * N + colBase + bc]
                          : make_float4(0.f, 0.f, 0.f, 0.f);
        }
#pragma unroll
        for (int k = 0; k < 8; k++) {
            ulonglong2 B0 = *(const ulonglong2*)&Bs[cur][k][tx * 8];
            ulonglong2 B1 = *(const ulonglong2*)&Bs[cur][k][tx * 8 + 4];
#pragma unroll
            for (int m = 0; m < 8; m++) {
                unsigned long long a2 =
                    *(const unsigned long long*)&As[cur][k][2 * (ty * 8 + m)];
                FMA2(acc[m][0], a2, B0.x);
                FMA2(acc[m][1], a2, B0.y);
                FMA2(acc[m][2], a2, B1.x);
                FMA2(acc[m][3], a2, B1.y);
            }
        }
        if (kt + 1 < KT) {
            const int nxt = cur ^ 1;
            *(float2*)&As[nxt][ac + 0][2 * ar] = make_float2(aF.x, aF.x);
            *(float2*)&As[nxt][ac + 1][2 * ar] = make_float2(aF.y, aF.y);
            *(float2*)&As[nxt][ac + 2][2 * ar] = make_float2(aF.z, aF.z);
            *(float2*)&As[nxt][ac + 3][2 * ar] = make_float2(aF.w, aF.w);
            *(float4*)&Bs[nxt][br][bc] = bF;
            __syncthreads();
        }
    }

    if (MODE == 1 || MODE == 3) {
        float bcol[8];
#pragma unroll
        for (int n = 0; n < 8; n++) bcol[n] = bias[colBase + tx * 8 + n];
#pragma unroll
        for (int m = 0; m < 8; m++) {
            int gr = rowBase + ty * 8 + m;
#pragma unroll
            for (int p = 0; p < 4; p++) {
                float x0, x1;
                asm("mov.b64 {%0,%1}, %2;" : "=f"(x0), "=f"(x1) : "l"(acc[m][p]));
                x0 += bcol[2 * p];
                x1 += bcol[2 * p + 1];
                float s0 = 1.f / (1.f + __expf(-x0));
                float s1v = 1.f / (1.f + __expf(-x1));
                int gc = colBase + tx * 8 + 2 * p;
                *(float2*)&out0[gr * N + gc] = make_float2(x0 * s0, x1 * s1v);
                *(float2*)&out1[gr * N + gc] =
                    make_float2(s0 * (1.f + x0 * (1.f - s0)),
                                s1v * (1.f + x1 * (1.f - s1v)));
            }
        }
    } else {  // MODE 0: fused divergence partial
#pragma unroll
        for (int m = 0; m < 8; m++) {
            int gr = rowBase + ty * 8 + m;
            const float* sp = s2d + gr * N + colBase + tx * 8;
            float rsum = 0.f;
#pragma unroll
            for (int p = 0; p < 4; p++) {
                float x0, x1;
                asm("mov.b64 {%0,%1}, %2;" : "=f"(x0), "=f"(x1) : "l"(acc[m][p]));
                float2 sv = *(const float2*)&sp[2 * p];
                rsum += x0 * sv.x + x1 * sv.y;
            }
            // reduce across the 16 tx-lanes (same ty within half-warp)
            rsum += __shfl_xor_sync(0xffffffffu, rsum, 8);
            rsum += __shfl_xor_sync(0xffffffffu, rsum, 4);
            rsum += __shfl_xor_sync(0xffffffffu, rsum, 2);
            rsum += __shfl_xor_sync(0xffffffffu, rsum, 1);
            if (tx == 0) dpart[blockIdx.x * Bsz + gr] = rsum;
        }
    }
}

// layer 3: out[b, 0:66] = h2[b,:] @ W3 + b3 ; BM=32 -> 128 blocks (full wave)
__global__ void __launch_bounds__(256)
gemm_l3(const float* __restrict__ A, const float* __restrict__ W3,
        const float* __restrict__ b3, float* __restrict__ out)
{
    __shared__ float As[16][33];
    __shared__ float Bs[16][80];
    const int tid = threadIdx.x;
    const int tx = tid & 15;
    const int ty = tid >> 4;
    const int rowBase = blockIdx.x * 32;

    float acc[2][5];
#pragma unroll
    for (int i = 0; i < 2; i++)
#pragma unroll
        for (int j = 0; j < 5; j++) acc[i][j] = 0.f;

    for (int k0 = 0; k0 < Hh; k0 += 16) {
        __syncthreads();
#pragma unroll
        for (int i = 0; i < 2; i++) {
            int e = i * 256 + tid;
            int r = e >> 4, c = e & 15;
            As[c][r] = A[(rowBase + r) * Hh + k0 + c];
        }
#pragma unroll
        for (int c = tx; c < 80; c += 16)
            Bs[ty][c] = (c < Dd) ? W3[(k0 + ty) * Dd + c] : 0.f;
        __syncthreads();
#pragma unroll
        for (int k = 0; k < 16; k++) {
            float a0 = As[k][ty * 2], a1 = As[k][ty * 2 + 1];
#pragma unroll
            for (int j = 0; j < 5; j++) {
                float b = Bs[k][tx + j * 16];
                acc[0][j] = fmaf(a0, b, acc[0][j]);
                acc[1][j] = fmaf(a1, b, acc[1][j]);
            }
        }
    }
#pragma unroll
    for (int i = 0; i < 2; i++) {
        int gr = rowBase + ty * 2 + i;
#pragma unroll
        for (int j = 0; j < 5; j++) {
            int c = tx + j * 16;
            if (c < Dd) out[gr * Dd + c] = acc[i][j] + b3[c];
        }
    }
}

// out[b] = -(sum of 4 column-block partials)   (deterministic)
__global__ void div_finish(const float* __restrict__ dp, float* __restrict__ out) {
    int b = blockIdx.x * 256 + threadIdx.x;
    out[b] = -(dp[b] + dp[Bsz + b] + dp[2 * Bsz + b] + dp[3 * Bsz + b]);
}

extern "C" void kernel_launch(void* const* d_in, const int* in_sizes, int n_in,
                              void* d_out, int out_size) {
    const float* xs = (const float*)d_in[0];
    const float* t  = (const float*)d_in[1];
    const float* W1 = (const float*)d_in[2];
    const float* b1 = (const float*)d_in[3];
    const float* W2 = (const float*)d_in[4];
    const float* b2 = (const float*)d_in[5];
    const float* W3 = (const float*)d_in[6];
    const float* b3 = (const float*)d_in[7];
    float* out = (float*)d_out;

    float *h1, *s1, *h2, *s2, *C, *dp;
    cudaGetSymbolAddress((void**)&h1, g_h1);
    cudaGetSymbolAddress((void**)&s1, g_s1);
    cudaGetSymbolAddress((void**)&h2, g_h2);
    cudaGetSymbolAddress((void**)&s2, g_s2);
    cudaGetSymbolAddress((void**)&C,  g_C);
    cudaGetSymbolAddress((void**)&dp, g_dp);

    // C = W2 .* (W3 @ W1[:D])^T   (batch-independent)
    precompute_C<<<dim3(16, 64), dim3(32, 8)>>>(W1, W2, W3);

    // layer 1: a1 = [xs|t] @ W1 + b1 ; h1 = silu(a1), s1 = silu'(a1)
    gemm2<3><<<dim3(4, 32), 256>>>(xs, t, W1, b1, h1, s1, nullptr, nullptr, Dd + 1);
    // layer 2: a2 = h1 @ W2 + b2 ; h2 = silu(a2), s2 = silu'(a2)
    gemm2<1><<<dim3(4, 32), 256>>>(h1, nullptr, W2, b2, h2, s2, nullptr, nullptr, Hh);
    // layer 3: dxs = h2 @ W3 + b3 -> d_out[0 : B*D]
    gemm_l3<<<128, 256>>>(h2, W3, b3, out);
    // div partials: (s1 @ C) . s2 rowwise -> dp[4][B]
    gemm2<0><<<dim3(4, 32), 256>>>(s1, nullptr, C, nullptr, nullptr, nullptr, s2, dp, Hh);
    // -div -> d_out[B*D : B*D + B]
    div_finish<<<16, 256>>>(dp, out + Bsz * Dd);
}

// round 11
// speedup vs baseline: 2.1204x; 1.8471x over previous
#include <cuda_runtime.h>
#include <cuda_bf16.h>
#include <cstdint>

#define Bsz 4096
#define Dd  66
#define Hh  512
#define K1P 128      // padded K for layer 1 (66 + 1 + zeros)

// tcgen05 is arch-specific: only emit it in the sm_103a (or sm_100a) pass.
// The compute_103 PTX pass compiles a stub; runtime loads the sm_103a cubin.
#if defined(__CUDA_ARCH_FEAT_SM103_ALL) || defined(__CUDA_ARCH_FEAT_SM100_ALL) || \
    (defined(__CUDA_ARCH_SPECIFIC__) && defined(__CUDA_ARCH__) && (__CUDA_ARCH__ >= 1000))
#define HAS_TCGEN05 1
#else
#define HAS_TCGEN05 0
#endif

typedef __nv_bfloat16 bf16;

// ---------------- scratch (__device__ globals; allocation-free rule) ---------
__device__ bf16  g_A0h[Bsz*K1P], g_A0l[Bsz*K1P];
__device__ bf16  g_W1h[Hh*K1P],  g_W1l[Hh*K1P];     // W1^T padded [512 x 128]
__device__ bf16  g_W2h[Hh*Hh],   g_W2l[Hh*Hh];      // W2^T [512 x 512]
__device__ bf16  g_W3h[128*Hh],  g_W3l[128*Hh];     // W3^T padded [128 x 512]
__device__ bf16  g_Chb[Hh*Hh],   g_Clb[Hh*Hh];      // C^T  [512 x 512]
__device__ bf16  g_h1h[Bsz*Hh],  g_h1l[Bsz*Hh];
__device__ bf16  g_s1h[Bsz*Hh],  g_s1l[Bsz*Hh];
__device__ bf16  g_h2h[Bsz*Hh],  g_h2l[Bsz*Hh];
__device__ float g_s2[Bsz*Hh];
__device__ float g_C [Hh*Hh];
__device__ float g_dp[4*Bsz];

// ---------------- helpers ----------------------------------------------------
__device__ __forceinline__ uint32_t smem_u32(const void* p) {
    uint32_t a;
    asm("{ .reg .u64 t; cvta.to.shared.u64 t, %1; cvt.u32.u64 %0, t; }" : "=r"(a) : "l"(p));
    return a;
}
__device__ __forceinline__ uint32_t sw128(uint32_t o) { return o ^ ((o >> 3) & 0x70); }
__device__ __forceinline__ void split2(float v, bf16& h, bf16& l) {
    h = __float2bfloat16(v);
    l = __float2bfloat16(v - __bfloat162float(h));
}

#if HAS_TCGEN05
__device__ __forceinline__ uint32_t elect_one() {
    uint32_t p;
    asm volatile("{\n\t.reg .pred p;\n\telect.sync _|p, 0xFFFFFFFF;\n\t"
                 "selp.b32 %0, 1, 0, p;\n\t}" : "=r"(p));
    return p;
}
__device__ __forceinline__ uint64_t mkdesc(uint32_t addr) {
    // SW128, version=1(Blackwell), SBO=64, LBO=1
    return 0x4000404000010000ull | ((uint64_t)(addr >> 4) & 0x3FFF);
}
__device__ __forceinline__ void mma_bf16_ss(uint32_t d, uint64_t ad, uint64_t bd,
                                            uint32_t idesc, uint32_t en) {
    asm volatile("{\n\t.reg .pred p;\n\tsetp.ne.u32 p, %4, 0;\n\t"
        "tcgen05.mma.cta_group::1.kind::f16 [%0], %1, %2, %3, {%5,%5,%5,%5}, p;\n\t}"
        :: "r"(d), "l"(ad), "l"(bd), "r"(idesc), "r"(en), "r"(0u) : "memory");
}
#define TCALLOC(sp, n)  asm volatile("tcgen05.alloc.cta_group::1.sync.aligned.shared::cta.b32 [%0], %1;" :: "r"(sp), "r"(n) : "memory")
#define TCDEALLOC(t, n) asm volatile("tcgen05.dealloc.cta_group::1.sync.aligned.b32 %0, %1;" :: "r"(t), "r"(n))
#define TCRELINQ()      asm volatile("tcgen05.relinquish_alloc_permit.cta_group::1.sync.aligned;")
#define TCCOMMIT(mb)    asm volatile("tcgen05.commit.cta_group::1.mbarrier::arrive::one.shared::cluster.b64 [%0];" :: "r"(mb) : "memory")
#define MBINIT(mb, n)   asm volatile("mbarrier.init.shared.b64 [%0], %1;" :: "r"(mb), "r"(n) : "memory")
#define FENCE_ASYNC()   asm volatile("fence.proxy.async.shared::cta;" ::: "memory")
#define TCFENCE_AFTER() asm volatile("tcgen05.fence::after_thread_sync;" ::: "memory")
#define TCFENCE_BEFORE() asm volatile("tcgen05.fence::before_thread_sync;" ::: "memory")
#define TCWAIT_LD()     asm volatile("tcgen05.wait::ld.sync.aligned;" ::: "memory")

__device__ __forceinline__ void mbar_wait(uint32_t mb, uint32_t parity) {
    uint32_t done;
    asm volatile("{\n\t.reg .pred p;\n\t"
        "mbarrier.try_wait.parity.acquire.cta.shared::cta.b64 p, [%1], %2;\n\t"
        "selp.b32 %0, 1, 0, p;\n\t}" : "=r"(done) : "r"(mb), "r"(parity) : "memory");
    if (!done) {
        asm volatile("{\n\t.reg .pred P1;\n\tWL_%=:\n\t"
            "mbarrier.try_wait.parity.acquire.cta.shared::cta.b64 P1, [%0], %1, 0x989680;\n\t"
            "@P1 bra.uni WD_%=;\n\tbra.uni WL_%=;\n\tWD_%=:\n\t}"
            :: "r"(mb), "r"(parity) : "memory");
    }
}
#define LDTM32(r, a) \
    asm volatile("tcgen05.ld.sync.aligned.32x32b.x32.b32 " \
        "{%0,%1,%2,%3,%4,%5,%6,%7,%8,%9,%10,%11,%12,%13,%14,%15," \
        "%16,%17,%18,%19,%20,%21,%22,%23,%24,%25,%26,%27,%28,%29,%30,%31}, [%32];" \
        : "=r"((r)[0]),"=r"((r)[1]),"=r"((r)[2]),"=r"((r)[3]),"=r"((r)[4]),"=r"((r)[5]), \
          "=r"((r)[6]),"=r"((r)[7]),"=r"((r)[8]),"=r"((r)[9]),"=r"((r)[10]),"=r"((r)[11]), \
          "=r"((r)[12]),"=r"((r)[13]),"=r"((r)[14]),"=r"((r)[15]),"=r"((r)[16]),"=r"((r)[17]), \
          "=r"((r)[18]),"=r"((r)[19]),"=r"((r)[20]),"=r"((r)[21]),"=r"((r)[22]),"=r"((r)[23]), \
          "=r"((r)[24]),"=r"((r)[25]),"=r"((r)[26]),"=r"((r)[27]),"=r"((r)[28]),"=r"((r)[29]), \
          "=r"((r)[30]),"=r"((r)[31]) : "r"(a))
#endif  // HAS_TCGEN05

// ---------------- conversion kernels ----------------------------------------
// C[i,j] = W2[i,j] * sum_d W3[j,d] * W1[d,i]
__global__ void precompute_C(const float* __restrict__ W1,
                             const float* __restrict__ W2,
                             const float* __restrict__ W3) {
    int j = blockIdx.x * 32 + threadIdx.x;
    int i = blockIdx.y * 8  + threadIdx.y;
    float acc = 0.f;
#pragma unroll
    for (int d = 0; d < Dd; d++)
        acc = fmaf(W3[j * Dd + d], W1[d * Hh + i], acc);
    g_C[i * Hh + j] = W2[i * Hh + j] * acc;
}

// transpose + bf16 split: out[n, k] = W[k, n] for k<KS, n<NS else 0; out is [.. x KP]
__global__ void conv_T(const float* __restrict__ W, bf16* __restrict__ oh,
                       bf16* __restrict__ ol, int KS, int NS, int NW, int KP) {
    __shared__ float tile[32][33];
    int k0 = blockIdx.x * 32, n0 = blockIdx.y * 32;
    int tx = threadIdx.x, ty = threadIdx.y;
#pragma unroll
    for (int i = 0; i < 32; i += 8) {
        int k = k0 + ty + i, n = n0 + tx;
        tile[ty + i][tx] = (k < KS && n < NS) ? W[k * NW + n] : 0.f;
    }
    __syncthreads();
#pragma unroll
    for (int i = 0; i < 32; i += 8) {
        int n = n0 + ty + i, k = k0 + tx;
        bf16 h, l; split2(tile[tx][ty + i], h, l);
        oh[n * KP + k] = h; ol[n * KP + k] = l;
    }
}

// A0 = concat([xs, t], pad to 128) -> bf16 hi/lo
__global__ void conv_A0(const float* __restrict__ xs, const float* __restrict__ t,
                        bf16* __restrict__ ah, bf16* __restrict__ al) {
    int i = blockIdx.x * 256 + threadIdx.x;
    int b = i >> 7, k = i & 127;
    float v = (k < Dd) ? xs[b * Dd + k] : ((k == Dd) ? t[b] : 0.f);
    bf16 h, l; split2(v, h, l);
    ah[i] = h; al[i] = l;
}

// ---------------- tcgen05 GEMM ----------------------------------------------
// D[128x128] = A[128xK] @ B^T (B stored [N=128 rows x K]) via 2-term bf16 split.
// MODE 0: epilogue silu: h->o0h/o0l (bf16), silu'->o1h/o1l (bf16)     (layer 1)
// MODE 1: epilogue silu: h->o0h/o0l (bf16), silu'->of32 (fp32)        (layer 2)
// MODE 2: epilogue bias only, cols<66 -> of32                         (layer 3)
// MODE 3: epilogue row-dot with s2f -> dpart                          (u/div)
#define IDESC 0x8200490u
#define STAGEB 65536
#define T16K   16384
#define SMEM_SZ 133120

template<int MODE>
__global__ void __launch_bounds__(256, 1)
mma_gemm(const bf16* __restrict__ Ah, const bf16* __restrict__ Al,
         const bf16* __restrict__ Bh, const bf16* __restrict__ Bl,
         const float* __restrict__ bias,
         bf16* __restrict__ o0h, bf16* __restrict__ o0l,
         bf16* __restrict__ o1h, bf16* __restrict__ o1l,
         float* __restrict__ of32, const float* __restrict__ s2f,
         float* __restrict__ dpart, int KA, int KB, int NC)
{
#if HAS_TCGEN05
    extern __shared__ char smc[];
    const uint32_t up0 = smem_u32(smc);
    const uint32_t tb  = (up0 + 1024u) & ~1023u;     // 1024-aligned tile base
    char* tilec = smc + (tb - up0);
    // one mbarrier PER STAGE: at most one outstanding completion per barrier,
    // so try_wait.parity can never alias (phase flips at most once per wait).
    const uint32_t mb0 = up0 + 8;
    const uint32_t mb1 = up0 + 16;

    const int tid = threadIdx.x;
    const int wid = tid >> 5;
    const int rowBase = blockIdx.y * 128;
    const int colBase = blockIdx.x * 128;

    if (wid == 0) { TCALLOC(up0, 128u); TCRELINQ(); }
    if (tid == 0) { MBINIT(mb0, 1u); MBINIT(mb1, 1u); }
    __syncthreads();
    uint32_t tmem;
    asm volatile("ld.shared.b32 %0, [%1];" : "=r"(tmem) : "r"(up0));

    const int r    = tid >> 1;          // 0..127 (A row / B row)
    const int half = tid & 1;           // which 32-elem (64B) half of the 128B row

    // ---- load chunk 0 into stage 0
    {
        const bf16* pa_h = Ah + (size_t)(rowBase + r) * KA + half * 32;
        const bf16* pa_l = Al + (size_t)(rowBase + r) * KA + half * 32;
        const bf16* pb_h = Bh + (size_t)(colBase + r) * KB + half * 32;
        const bf16* pb_l = Bl + (size_t)(colBase + r) * KB + half * 32;
        uint32_t off = (uint32_t)r * 128 + half * 64;
#pragma unroll
        for (int q = 0; q < 4; q++) {
            uint32_t so = sw128(off + q * 16);
            *(uint4*)(tilec + 0 * T16K + so) = *(const uint4*)(pa_h + q * 8);
            *(uint4*)(tilec + 1 * T16K + so) = *(const uint4*)(pa_l + q * 8);
            *(uint4*)(tilec + 2 * T16K + so) = *(const uint4*)(pb_h + q * 8);
            *(uint4*)(tilec + 3 * T16K + so) = *(const uint4*)(pb_l + q * 8);
        }
    }
    FENCE_ASYNC();
    __syncthreads();

    for (int c = 0; c < NC; c++) {
        const uint32_t st = c & 1;
        // issue 12 MMAs on buf st; commit #c arrives on mb[st]
        if (wid == 0 && elect_one()) {
            uint32_t ab = tb + st * STAGEB;
            uint64_t dAh = mkdesc(ab), dAl = mkdesc(ab + T16K);
            uint64_t dBh = mkdesc(ab + 2 * T16K), dBl = mkdesc(ab + 3 * T16K);
            uint32_t en = (c == 0) ? 0u : 1u;
#pragma unroll
            for (int k = 0; k < 4; k++) {
                mma_bf16_ss(tmem, dAh + 2 * k, dBh + 2 * k, IDESC, en); en = 1u;
                mma_bf16_ss(tmem, dAh + 2 * k, dBl + 2 * k, IDESC, 1u);
                mma_bf16_ss(tmem, dAl + 2 * k, dBh + 2 * k, IDESC, 1u);
            }
            TCCOMMIT(st ? mb1 : mb0);
        }
        if (c + 1 < NC) {
            const int k0 = (c + 1) * 64;
            // prefetch to regs
            const bf16* pa_h = Ah + (size_t)(rowBase + r) * KA + k0 + half * 32;
            const bf16* pa_l = Al + (size_t)(rowBase + r) * KA + k0 + half * 32;
            const bf16* pb_h = Bh + (size_t)(colBase + r) * KB + k0 + half * 32;
            const bf16* pb_l = Bl + (size_t)(colBase + r) * KB + k0 + half * 32;
            uint4 va[4], vb[4], vc[4], vd[4];
#pragma unroll
            for (int q = 0; q < 4; q++) {
                va[q] = *(const uint4*)(pa_h + q * 8);
                vb[q] = *(const uint4*)(pa_l + q * 8);
                vc[q] = *(const uint4*)(pb_h + q * 8);
                vd[q] = *(const uint4*)(pb_l + q * 8);
            }
            // stage nxt=(c+1)&1 was last read by MMA #c-1 (committed on mb[nxt]).
            // Wait for the ((c-1)/2)-th completion of mb[nxt] -> parity ((c-1)>>1)&1.
            const uint32_t nxt = (c + 1) & 1;
            if (c >= 1) mbar_wait(nxt ? mb1 : mb0, (uint32_t)(((c - 1) >> 1) & 1));
            char* nb = tilec + nxt * STAGEB;
            uint32_t off = (uint32_t)r * 128 + half * 64;
#pragma unroll
            for (int q = 0; q < 4; q++) {
                uint32_t so = sw128(off + q * 16);
                *(uint4*)(nb + 0 * T16K + so) = va[q];
                *(uint4*)(nb + 1 * T16K + so) = vb[q];
                *(uint4*)(nb + 2 * T16K + so) = vc[q];
                *(uint4*)(nb + 3 * T16K + so) = vd[q];
            }
            FENCE_ASYNC();
        }
        __syncthreads();
    }
    // final: commit #NC-1 on mb[(NC-1)&1]; it is completion #((NC-1)>>1) there.
    // tcgen05.commit covers ALL previously issued MMAs, so this wait suffices.
    mbar_wait(((NC - 1) & 1) ? mb1 : mb0, (uint32_t)(((NC - 1) >> 1) & 1));
    TCFENCE_AFTER();
    __syncthreads();

    // ---- MODE 3: stage s2 tile into smem (MMA done; smem free) -------------
    float* s2s = (float*)tilec;          // [128][129]
    if (MODE == 3) {
        for (int i = tid; i < 128 * 128; i += 256) {
            int rr = i >> 7, cc = i & 127;
            s2s[rr * 129 + cc] = s2f[(size_t)(rowBase + rr) * Hh + colBase + cc];
        }
        __syncthreads();
    }

    // ---- epilogue: 4 warps read D (128 cols fp32), lane = row ---------------
    if (tid < 128) {
        const int gr = rowBase + tid;     // warp w lane l -> row w*32+l = tid
        float rsum = 0.f;
#pragma unroll
        for (int ch = 0; ch < 4; ch++) {
            if (MODE == 2 && ch == 3) break;          // cols >= 96 unused
            uint32_t regs[32];
            LDTM32(regs, tmem + ch * 32);
            TCWAIT_LD();
            const int gcB = colBase + ch * 32;
            if (MODE == 0 || MODE == 1) {
#pragma unroll
                for (int cc = 0; cc < 32; cc += 2) {
                    float x0 = __uint_as_float(regs[cc])     + bias[gcB + cc];
                    float x1 = __uint_as_float(regs[cc + 1]) + bias[gcB + cc + 1];
                    float sg0 = 1.f / (1.f + __expf(-x0));
                    float sg1 = 1.f / (1.f + __expf(-x1));
                    float hh0 = x0 * sg0, hh1 = x1 * sg1;
                    float dd0 = sg0 * (1.f + x0 * (1.f - sg0));
                    float dd1 = sg1 * (1.f + x1 * (1.f - sg1));
                    size_t o = (size_t)gr * Hh + gcB + cc;
                    __nv_bfloat162 ph, pl;
                    bf16 th, tl;
                    split2(hh0, th, tl); ph.x = th; pl.x = tl;
                    split2(hh1, th, tl); ph.y = th; pl.y = tl;
                    *(__nv_bfloat162*)&o0h[o] = ph;
                    *(__nv_bfloat162*)&o0l[o] = pl;
                    if (MODE == 0) {
                        split2(dd0, th, tl); ph.x = th; pl.x = tl;
                        split2(dd1, th, tl); ph.y = th; pl.y = tl;
                        *(__nv_bfloat162*)&o1h[o] = ph;
                        *(__nv_bfloat162*)&o1l[o] = pl;
                    } else {
                        *(float2*)&of32[o] = make_float2(dd0, dd1);
                    }
                }
            } else if (MODE == 2) {
#pragma unroll
                for (int cc = 0; cc < 32; cc++) {
                    int gc = gcB + cc;
                    if (gc < Dd)
                        of32[(size_t)gr * Dd + gc] = __uint_as_float(regs[cc]) + bias[gc];
                }
            } else { // MODE 3
#pragma unroll
                for (int cc = 0; cc < 32; cc++)
                    rsum = fmaf(__uint_as_float(regs[cc]),
                                s2s[tid * 129 + ch * 32 + cc], rsum);
            }
        }
        if (MODE == 3) dpart[blockIdx.x * Bsz + gr] = rsum;
        TCFENCE_BEFORE();
    }
    __syncthreads();
    if (wid == 0) TCDEALLOC(tmem, 128u);
#endif  // HAS_TCGEN05
}

// out[b] = -(sum of 4 column-block partials)
__global__ void div_finish(const float* __restrict__ dp, float* __restrict__ out) {
    int b = blockIdx.x * 256 + threadIdx.x;
    out[b] = -(dp[b] + dp[Bsz + b] + dp[2 * Bsz + b] + dp[3 * Bsz + b]);
}

// ---------------- launch -----------------------------------------------------
extern "C" void kernel_launch(void* const* d_in, const int* in_sizes, int n_in,
                              void* d_out, int out_size) {
    const float* xs = (const float*)d_in[0];
    const float* t  = (const float*)d_in[1];
    const float* W1 = (const float*)d_in[2];
    const float* b1 = (const float*)d_in[3];
    const float* W2 = (const float*)d_in[4];
    const float* b2 = (const float*)d_in[5];
    const float* W3 = (const float*)d_in[6];
    const float* b3 = (const float*)d_in[7];
    float* out = (float*)d_out;

    bf16 *A0h,*A0l,*W1h,*W1l,*W2h,*W2l,*W3h,*W3l,*Chb,*Clb;
    bf16 *h1h,*h1l,*s1h,*s1l,*h2h,*h2l;
    float *s2, *C, *dp;
    cudaGetSymbolAddress((void**)&A0h, g_A0h); cudaGetSymbolAddress((void**)&A0l, g_A0l);
    cudaGetSymbolAddress((void**)&W1h, g_W1h); cudaGetSymbolAddress((void**)&W1l, g_W1l);
    cudaGetSymbolAddress((void**)&W2h, g_W2h); cudaGetSymbolAddress((void**)&W2l, g_W2l);
    cudaGetSymbolAddress((void**)&W3h, g_W3h); cudaGetSymbolAddress((void**)&W3l, g_W3l);
    cudaGetSymbolAddress((void**)&Chb, g_Chb); cudaGetSymbolAddress((void**)&Clb, g_Clb);
    cudaGetSymbolAddress((void**)&h1h, g_h1h); cudaGetSymbolAddress((void**)&h1l, g_h1l);
    cudaGetSymbolAddress((void**)&s1h, g_s1h); cudaGetSymbolAddress((void**)&s1l, g_s1l);
    cudaGetSymbolAddress((void**)&h2h, g_h2h); cudaGetSymbolAddress((void**)&h2l, g_h2l);
    cudaGetSymbolAddress((void**)&s2,  g_s2);
    cudaGetSymbolAddress((void**)&C,   g_C);
    cudaGetSymbolAddress((void**)&dp,  g_dp);

    cudaFuncSetAttribute(mma_gemm<0>, cudaFuncAttributeMaxDynamicSharedMemorySize, SMEM_SZ);
    cudaFuncSetAttribute(mma_gemm<1>, cudaFuncAttributeMaxDynamicSharedMemorySize, SMEM_SZ);
    cudaFuncSetAttribute(mma_gemm<2>, cudaFuncAttributeMaxDynamicSharedMemorySize, SMEM_SZ);
    cudaFuncSetAttribute(mma_gemm<3>, cudaFuncAttributeMaxDynamicSharedMemorySize, SMEM_SZ);

    // weight prep (batch-independent math is per-call but tiny)
    precompute_C<<<dim3(16, 64), dim3(32, 8)>>>(W1, W2, W3);
    conv_A0<<<(Bsz * K1P) / 256, 256>>>(xs, t, A0h, A0l);
    conv_T<<<dim3(K1P / 32, Hh / 32), dim3(32, 8)>>>(W1, W1h, W1l, Dd + 1, Hh, Hh, K1P);
    conv_T<<<dim3(Hh / 32, Hh / 32), dim3(32, 8)>>>(W2, W2h, W2l, Hh, Hh, Hh, Hh);
    conv_T<<<dim3(Hh / 32, 128 / 32), dim3(32, 8)>>>(W3, W3h, W3l, Hh, Dd, Dd, Hh);
    conv_T<<<dim3(Hh / 32, Hh / 32), dim3(32, 8)>>>(C,  Chb, Clb, Hh, Hh, Hh, Hh);

    // layer 1: [xs|t] @ W1 -> h1(hi/lo), s1(hi/lo)
    mma_gemm<0><<<dim3(4, 32), 256, SMEM_SZ>>>(A0h, A0l, W1h, W1l, b1,
        h1h, h1l, s1h, s1l, nullptr, nullptr, nullptr, K1P, K1P, 2);
    // layer 2: h1 @ W2 -> h2(hi/lo), s2(fp32)
    mma_gemm<1><<<dim3(4, 32), 256, SMEM_SZ>>>(h1h, h1l, W2h, W2l, b2,
        h2h, h2l, nullptr, nullptr, s2, nullptr, nullptr, Hh, Hh, 8);
    // layer 3: h2 @ W3 + b3 -> dxs
    mma_gemm<2><<<dim3(1, 32), 256, SMEM_SZ>>>(h2h, h2l, W3h, W3l, b3,
        nullptr, nullptr, nullptr, nullptr, out, nullptr, nullptr, Hh, Hh, 8);
    // u = s1 @ C, fused row-dot with s2 -> partials
    mma_gemm<3><<<dim3(4, 32), 256, SMEM_SZ>>>(s1h, s1l, Chb, Clb, nullptr,
        nullptr, nullptr, nullptr, nullptr, nullptr, s2, dp, Hh, Hh, 8);
    // -div
    div_finish<<<16, 256>>>(dp, out + Bsz * Dd);
}